// round 1
// baseline (speedup 1.0000x reference)
#include <cuda_runtime.h>
#include <math.h>

// Problem constants (fixed by setup_inputs)
#define S_LEN   2048
#define HID     4096
#define NH      32
#define NKV     8
#define HD      128
#define WINDOW  1024
#define SCALE_F 0.08838834764831845f   // 1/sqrt(128)

// ---------------------------------------------------------------------------
// Scratch (device globals — no allocation allowed)
// ---------------------------------------------------------------------------
__device__ float g_q  [S_LEN * NH  * HD];   // 32 MB
__device__ float g_k  [S_LEN * NKV * HD];   //  8 MB
__device__ float g_v  [S_LEN * NKV * HD];   //  8 MB
__device__ float g_att[S_LEN * NH  * HD];   // 32 MB
__device__ float g_cos[S_LEN * (HD / 2)];
__device__ float g_sin[S_LEN * (HD / 2)];

// ---------------------------------------------------------------------------
// GEMM: C[M,N] = A[M,K] @ B[K,N], row-major fp32.
// Block tile 128x64, K-tile 16, 256 threads, 8x4 per thread.
// Requires M%128==0, N%64==0, K%16==0 (true for all our shapes).
// ---------------------------------------------------------------------------
__global__ __launch_bounds__(256) void gemm_kernel(
    const float* __restrict__ A, const float* __restrict__ B,
    float* __restrict__ C, int M, int N, int K)
{
    __shared__ float As[16][132];  // [BK][BM + 4 pad], transposed A tile
    __shared__ float Bs[16][64];   // [BK][BN]

    const int tid = threadIdx.x;
    const int bm = blockIdx.y * 128;
    const int bn = blockIdx.x * 64;
    const int ty = tid >> 4;       // 0..15
    const int tx = tid & 15;       // 0..15

    float acc[8][4];
#pragma unroll
    for (int m = 0; m < 8; m++)
#pragma unroll
        for (int n = 0; n < 4; n++) acc[m][n] = 0.f;

    for (int k0 = 0; k0 < K; k0 += 16) {
        // Load A tile (128x16) transposed into As — 2 float4 per thread
#pragma unroll
        for (int it = 0; it < 2; it++) {
            int e = tid + 256 * it;          // float4 index, 0..511
            int row = e >> 2;                // 0..127
            int kq  = (e & 3) << 2;          // 0,4,8,12
            float4 v = *(const float4*)(A + (size_t)(bm + row) * K + k0 + kq);
            As[kq + 0][row] = v.x;
            As[kq + 1][row] = v.y;
            As[kq + 2][row] = v.z;
            As[kq + 3][row] = v.w;
        }
        // Load B tile (16x64) — 1 float4 per thread
        {
            int krow = tid >> 4;             // 0..15
            int col  = (tid & 15) << 2;      // 0..60
            *(float4*)&Bs[krow][col] =
                *(const float4*)(B + (size_t)(k0 + krow) * N + bn + col);
        }
        __syncthreads();

#pragma unroll
        for (int kk = 0; kk < 16; kk++) {
            float a[8], b[4];
            *(float4*)&a[0] = *(const float4*)&As[kk][ty * 8];
            *(float4*)&a[4] = *(const float4*)&As[kk][ty * 8 + 4];
            *(float4*)&b[0] = *(const float4*)&Bs[kk][tx * 4];
#pragma unroll
            for (int m = 0; m < 8; m++)
#pragma unroll
                for (int n = 0; n < 4; n++)
                    acc[m][n] += a[m] * b[n];
        }
        __syncthreads();
    }

#pragma unroll
    for (int m = 0; m < 8; m++) {
        float4 v = make_float4(acc[m][0], acc[m][1], acc[m][2], acc[m][3]);
        *(float4*)(C + (size_t)(bm + ty * 8 + m) * N + bn + tx * 4) = v;
    }
}

// ---------------------------------------------------------------------------
// RoPE tables. position_ids is arange(S) by construction; angles computed in
// double then applied in fp32 to match the fp32 reference closely.
// ---------------------------------------------------------------------------
__global__ void rope_tables_kernel()
{
    int s = blockIdx.x;
    int d = threadIdx.x;           // 0..63
    double invf = pow(10000.0, -(double)(2 * d) / 128.0);
    float  ang  = (float)s * (float)invf;     // fp32 angle (matches jnp)
    g_cos[s * 64 + d] = (float)cos((double)ang);
    g_sin[s * 64 + d] = (float)sin((double)ang);
}

__global__ void rope_apply_kernel(float* __restrict__ x, int nheads)
{
    int idx = blockIdx.x * 256 + threadIdx.x;
    int total = S_LEN * nheads * 64;
    if (idx >= total) return;
    int d = idx & 63;
    int t = idx >> 6;
    int h = t % nheads;
    int s = t / nheads;
    float c  = g_cos[s * 64 + d];
    float sn = g_sin[s * 64 + d];
    float* p = x + ((size_t)s * nheads + h) * HD;
    float x0 = p[d];
    float x1 = p[d + 64];
    p[d]      = x0 * c - x1 * sn;
    p[d + 64] = x1 * c + x0 * sn;
}

// ---------------------------------------------------------------------------
// Flash attention with analytic sliding-window causal mask.
// One block per (q-tile of 64, head). 256 threads.
// Smem: Qs/Ks transposed [128][68], Vs [64][132], Ss [64][68], m/l/f rows.
// ---------------------------------------------------------------------------
#define ATT_SMEM_FLOATS (128*68 + 128*68 + 64*132 + 64*68 + 3*64)

__global__ __launch_bounds__(256) void attn_kernel(
    const float* __restrict__ q, const float* __restrict__ k,
    const float* __restrict__ v, float* __restrict__ o)
{
    extern __shared__ float sm[];
    float* Qs   = sm;                 // [128][68] d-major
    float* Ks   = Qs + 128 * 68;      // [128][68] d-major
    float* Vs   = Ks + 128 * 68;      // [64][132] j-major
    float* Ss   = Vs + 64 * 132;      // [64][68]  i-major (scores -> probs)
    float* mrow = Ss + 64 * 68;
    float* lrow = mrow + 64;
    float* frow = lrow + 64;

    const int tid = threadIdx.x;
    const int q0  = blockIdx.x * 64;
    const int h   = blockIdx.y;
    const int hk  = h >> 2;           // GQA: 4 q-heads per kv-head
    const int ty  = tid >> 4;         // 0..15
    const int tx  = tid & 15;         // 0..15

    // Load Q tile transposed: Qs[d][i]
#pragma unroll
    for (int it = 0; it < 8; it++) {
        int e   = tid + 256 * it;     // 0..2047 float4 index
        int row = e >> 5;             // 0..63
        int dq  = (e & 31) << 2;      // 0..124
        float4 qq = *(const float4*)(q + ((size_t)(q0 + row) * NH + h) * HD + dq);
        Qs[(dq + 0) * 68 + row] = qq.x;
        Qs[(dq + 1) * 68 + row] = qq.y;
        Qs[(dq + 2) * 68 + row] = qq.z;
        Qs[(dq + 3) * 68 + row] = qq.w;
    }
    if (tid < 64) { mrow[tid] = -1e30f; lrow[tid] = 0.f; }

    float acc[4][8];
#pragma unroll
    for (int m = 0; m < 4; m++)
#pragma unroll
        for (int n = 0; n < 8; n++) acc[m][n] = 0.f;

    int lo = q0 - (WINDOW - 1);
    if (lo < 0) lo = 0;
    const int jt_lo = lo >> 6;
    const int jt_hi = q0 >> 6;

    for (int jt = jt_lo; jt <= jt_hi; jt++) {
        const int j0 = jt << 6;
        __syncthreads();   // protect Ks/Vs/Ss against previous iteration readers

        // Load K transposed (Ks[d][j]) and V direct (Vs[j][d])
#pragma unroll
        for (int it = 0; it < 8; it++) {
            int e   = tid + 256 * it;
            int row = e >> 5;
            int dq  = (e & 31) << 2;
            size_t gbase = ((size_t)(j0 + row) * NKV + hk) * HD + dq;
            float4 kk4 = *(const float4*)(k + gbase);
            Ks[(dq + 0) * 68 + row] = kk4.x;
            Ks[(dq + 1) * 68 + row] = kk4.y;
            Ks[(dq + 2) * 68 + row] = kk4.z;
            Ks[(dq + 3) * 68 + row] = kk4.w;
            *(float4*)(Vs + row * 132 + dq) = *(const float4*)(v + gbase);
        }
        __syncthreads();

        // Scores: S[i][j] = Q[i]·K[j]; thread computes 4x4
        float s[4][4];
#pragma unroll
        for (int m = 0; m < 4; m++)
#pragma unroll
            for (int n = 0; n < 4; n++) s[m][n] = 0.f;

#pragma unroll 4
        for (int d = 0; d < 128; d++) {
            float4 a = *(const float4*)(Qs + d * 68 + ty * 4);
            float4 b = *(const float4*)(Ks + d * 68 + tx * 4);
            s[0][0] += a.x * b.x; s[0][1] += a.x * b.y; s[0][2] += a.x * b.z; s[0][3] += a.x * b.w;
            s[1][0] += a.y * b.x; s[1][1] += a.y * b.y; s[1][2] += a.y * b.z; s[1][3] += a.y * b.w;
            s[2][0] += a.z * b.x; s[2][1] += a.z * b.y; s[2][2] += a.z * b.z; s[2][3] += a.z * b.w;
            s[3][0] += a.w * b.x; s[3][1] += a.w * b.y; s[3][2] += a.w * b.z; s[3][3] += a.w * b.w;
        }
        // scale + analytic mask, store to Ss
#pragma unroll
        for (int m = 0; m < 4; m++) {
            int gi = q0 + ty * 4 + m;
#pragma unroll
            for (int n = 0; n < 4; n++) {
                int gj = j0 + tx * 4 + n;
                bool allowed = (gj <= gi) && (gj > gi - WINDOW);
                Ss[(ty * 4 + m) * 68 + tx * 4 + n] =
                    allowed ? s[m][n] * SCALE_F : -1e9f;
            }
        }
        __syncthreads();

        // Online softmax: 4 threads per row
        {
            int r    = tid >> 2;
            int part = tid & 3;
            float* srow = Ss + r * 68 + part * 16;
            float mx = -1e30f;
#pragma unroll
            for (int jj = 0; jj < 16; jj++) mx = fmaxf(mx, srow[jj]);
            mx = fmaxf(mx, __shfl_xor_sync(0xffffffffu, mx, 1));
            mx = fmaxf(mx, __shfl_xor_sync(0xffffffffu, mx, 2));
            float mold = mrow[r];
            float mnew = fmaxf(mold, mx);
            float sum = 0.f;
#pragma unroll
            for (int jj = 0; jj < 16; jj++) {
                float vv = srow[jj];
                float p  = (vv > -1e8f) ? expf(vv - mnew) : 0.f;  // masked -> exactly 0
                srow[jj] = p;
                sum += p;
            }
            sum += __shfl_xor_sync(0xffffffffu, sum, 1);
            sum += __shfl_xor_sync(0xffffffffu, sum, 2);
            if (part == 0) {
                float f = expf(mold - mnew);
                lrow[r] = lrow[r] * f + sum;
                mrow[r] = mnew;
                frow[r] = f;
            }
        }
        __syncthreads();

        // Rescale accumulator, then O += P @ V  (thread: 4 rows x 8 dims)
#pragma unroll
        for (int m = 0; m < 4; m++) {
            float f = frow[ty * 4 + m];
#pragma unroll
            for (int n = 0; n < 8; n++) acc[m][n] *= f;
        }
#pragma unroll 2
        for (int j = 0; j < 64; j++) {
            float4 b0 = *(const float4*)(Vs + j * 132 + tx * 8);
            float4 b1 = *(const float4*)(Vs + j * 132 + tx * 8 + 4);
#pragma unroll
            for (int m = 0; m < 4; m++) {
                float p = Ss[(ty * 4 + m) * 68 + j];
                acc[m][0] += p * b0.x; acc[m][1] += p * b0.y;
                acc[m][2] += p * b0.z; acc[m][3] += p * b0.w;
                acc[m][4] += p * b1.x; acc[m][5] += p * b1.y;
                acc[m][6] += p * b1.z; acc[m][7] += p * b1.w;
            }
        }
    }

    // Epilogue: normalize and store [s][h][d]
#pragma unroll
    for (int m = 0; m < 4; m++) {
        float inv = 1.0f / lrow[ty * 4 + m];
        size_t base = ((size_t)(q0 + ty * 4 + m) * NH + h) * HD + tx * 8;
        float4 o0 = make_float4(acc[m][0] * inv, acc[m][1] * inv,
                                acc[m][2] * inv, acc[m][3] * inv);
        float4 o1 = make_float4(acc[m][4] * inv, acc[m][5] * inv,
                                acc[m][6] * inv, acc[m][7] * inv);
        *(float4*)(o + base)     = o0;
        *(float4*)(o + base + 4) = o1;
    }
}

// ---------------------------------------------------------------------------
// kernel_launch
// Inputs: 0=hidden_states 1=attention_mask(unused; analytic) 2=position_ids
//         (unused; arange by construction) 3=Wq 4=Wk 5=Wv 6=Wo
// ---------------------------------------------------------------------------
extern "C" void kernel_launch(void* const* d_in, const int* in_sizes, int n_in,
                              void* d_out, int out_size)
{
    (void)in_sizes; (void)n_in; (void)out_size;
    const float* hs = (const float*)d_in[0];
    const float* Wq = (const float*)d_in[3];
    const float* Wk = (const float*)d_in[4];
    const float* Wv = (const float*)d_in[5];
    const float* Wo = (const float*)d_in[6];
    float* out = (float*)d_out;

    float *q, *k, *v, *att;
    cudaGetSymbolAddress((void**)&q,   g_q);
    cudaGetSymbolAddress((void**)&k,   g_k);
    cudaGetSymbolAddress((void**)&v,   g_v);
    cudaGetSymbolAddress((void**)&att, g_att);

    // Q/K/V projections
    gemm_kernel<<<dim3(HID / 64, S_LEN / 128), 256>>>(hs, Wq, q,   S_LEN, HID,       HID);
    gemm_kernel<<<dim3((NKV*HD) / 64, S_LEN / 128), 256>>>(hs, Wk, k, S_LEN, NKV*HD, HID);
    gemm_kernel<<<dim3((NKV*HD) / 64, S_LEN / 128), 256>>>(hs, Wv, v, S_LEN, NKV*HD, HID);

    // RoPE
    rope_tables_kernel<<<S_LEN, 64>>>();
    rope_apply_kernel<<<(S_LEN * NH  * 64 + 255) / 256, 256>>>(q, NH);
    rope_apply_kernel<<<(S_LEN * NKV * 64 + 255) / 256, 256>>>(k, NKV);

    // Attention
    const int att_smem = ATT_SMEM_FLOATS * (int)sizeof(float);
    cudaFuncSetAttribute(attn_kernel,
                         cudaFuncAttributeMaxDynamicSharedMemorySize, att_smem);
    attn_kernel<<<dim3(S_LEN / 64, NH), 256, att_smem>>>(q, k, v, att);

    // Output projection
    gemm_kernel<<<dim3(HID / 64, S_LEN / 128), 256>>>(att, Wo, out, S_LEN, HID, HID);
}

// round 3
// speedup vs baseline: 1.6328x; 1.6328x over previous
#include <cuda_runtime.h>
#include <cuda_bf16.h>
#include <stdint.h>
#include <math.h>

typedef unsigned int u32;

// Problem constants (fixed by setup_inputs)
#define S_LEN   2048
#define HID     4096
#define NH      32
#define NKV     8
#define HD      128
#define WINDOW  1024
#define SCALE_F 0.08838834764831845f   // 1/sqrt(128)

// ---------------------------------------------------------------------------
// Scratch (device globals — no allocation allowed)
// ---------------------------------------------------------------------------
__device__ float g_q  [S_LEN * NH  * HD];   // 32 MB
__device__ float g_k  [S_LEN * NKV * HD];   //  8 MB
__device__ float g_v  [S_LEN * NKV * HD];   //  8 MB
__device__ float g_att[S_LEN * NH  * HD];   // 32 MB
__device__ float g_cos[S_LEN * (HD / 2)];
__device__ float g_sin[S_LEN * (HD / 2)];

// ---------------------------------------------------------------------------
// bf16x3 tensor-core GEMM: C[M,N] = A[M,K] @ B[K,N], fp32 in/out.
// x = x_hi + x_lo (both bf16); accumulate hi*hi + hi*lo + lo*hi in fp32
// via mma.sync.m16n8k16. Residual error ~1e-5 on the result.
//
// Block tile 128x128, BK=32, 256 threads = 8 warps (2x4 -> 64x32 warp tile).
// Smem pair-word layouts (32-bit words hold bf16 k-pairs):
//   As[m][kpair]  stride RSA=20 words
//   Bs[kpair][n]  stride RSB=136 words
// Requires M%128==0, N%128==0, K%32==0 (true for all shapes here).
// ---------------------------------------------------------------------------
#define RSA 20
#define RSB 136

__device__ __forceinline__ u32 pack_bf16(float e0, float e1) {
    __nv_bfloat162 p = __floats2bfloat162_rn(e0, e1);   // .x = e0 (low half)
    return *reinterpret_cast<u32*>(&p);
}

#define MMA_BF16(d, a0, a1, a2, a3, b0, b1)                                 \
    asm volatile(                                                           \
        "mma.sync.aligned.m16n8k16.row.col.f32.bf16.bf16.f32 "              \
        "{%0,%1,%2,%3}, {%4,%5,%6,%7}, {%8,%9}, {%0,%1,%2,%3};"             \
        : "+f"(d[0]), "+f"(d[1]), "+f"(d[2]), "+f"(d[3])                    \
        : "r"(a0), "r"(a1), "r"(a2), "r"(a3), "r"(b0), "r"(b1))

__global__ __launch_bounds__(256, 2) void gemm_bf16x3(
    const float* __restrict__ A, const float* __restrict__ B,
    float* __restrict__ C, int M, int N, int K)
{
    __shared__ u32 AsHi[128 * RSA];
    __shared__ u32 AsLo[128 * RSA];
    __shared__ u32 BsHi[16 * RSB];
    __shared__ u32 BsLo[16 * RSB];

    const int tid  = threadIdx.x;
    const int warp = tid >> 5;
    const int lane = tid & 31;
    const int wm   = (warp >> 2) * 64;   // 0 / 64
    const int wn   = (warp & 3)  * 32;   // 0..96
    const int bm   = blockIdx.y * 128;
    const int bn   = blockIdx.x * 128;

    const int r = lane >> 2;   // 0..7  (fragment row group)
    const int t = lane & 3;    // 0..3  (fragment k-pair group)

    float acc[4][4][4];
#pragma unroll
    for (int mi = 0; mi < 4; mi++)
#pragma unroll
        for (int ni = 0; ni < 4; ni++)
#pragma unroll
            for (int c = 0; c < 4; c++) acc[mi][ni][c] = 0.f;

    // B loader: thread -> kpair = tid>>4 (0..15), n0 = (tid&15)*8
    const int b_kp = tid >> 4;
    const int b_n0 = (tid & 15) * 8;

    for (int k0 = 0; k0 < K; k0 += 32) {
        // ---- load A tile (128x32 fp32 -> hi/lo bf16 pair-words) ----
#pragma unroll
        for (int i = 0; i < 4; i++) {
            int e   = tid + 256 * i;           // 0..1023 float4 slots
            int row = e >> 3;                  // 0..127
            int c4  = e & 7;                   // float4 index in row
            float4 v = *(const float4*)(A + (size_t)(bm + row) * K + k0 + c4 * 4);
            float hx = __bfloat162float(__float2bfloat16_rn(v.x));
            float hy = __bfloat162float(__float2bfloat16_rn(v.y));
            float hz = __bfloat162float(__float2bfloat16_rn(v.z));
            float hw = __bfloat162float(__float2bfloat16_rn(v.w));
            uint2 hi = make_uint2(pack_bf16(hx, hy), pack_bf16(hz, hw));
            uint2 lo = make_uint2(pack_bf16(v.x - hx, v.y - hy),
                                  pack_bf16(v.z - hz, v.w - hw));
            *(uint2*)&AsHi[row * RSA + c4 * 2] = hi;
            *(uint2*)&AsLo[row * RSA + c4 * 2] = lo;
        }
        // ---- load B tile (32x128 fp32 -> pair-words along k) ----
        {
            const float* B0 = B + (size_t)(k0 + b_kp * 2) * N + bn + b_n0;
            const float* B1 = B0 + N;
            float4 u0 = *(const float4*)(B0);
            float4 u1 = *(const float4*)(B0 + 4);
            float4 w0 = *(const float4*)(B1);
            float4 w1 = *(const float4*)(B1 + 4);
            float ue[8] = {u0.x,u0.y,u0.z,u0.w,u1.x,u1.y,u1.z,u1.w};
            float we[8] = {w0.x,w0.y,w0.z,w0.w,w1.x,w1.y,w1.z,w1.w};
            u32 hiw[8], low[8];
#pragma unroll
            for (int j = 0; j < 8; j++) {
                float hu  = __bfloat162float(__float2bfloat16_rn(ue[j]));
                float hw2 = __bfloat162float(__float2bfloat16_rn(we[j]));
                hiw[j] = pack_bf16(hu, hw2);                 // (k even, k odd)
                low[j] = pack_bf16(ue[j] - hu, we[j] - hw2);
            }
            u32* dh = &BsHi[b_kp * RSB + b_n0];
            u32* dl = &BsLo[b_kp * RSB + b_n0];
            *(uint4*)(dh)     = make_uint4(hiw[0], hiw[1], hiw[2], hiw[3]);
            *(uint4*)(dh + 4) = make_uint4(hiw[4], hiw[5], hiw[6], hiw[7]);
            *(uint4*)(dl)     = make_uint4(low[0], low[1], low[2], low[3]);
            *(uint4*)(dl + 4) = make_uint4(low[4], low[5], low[6], low[7]);
        }
        __syncthreads();

        // ---- compute: two k16 steps ----
#pragma unroll
        for (int ks = 0; ks < 2; ks++) {
            u32 bH[4][2], bL[4][2];
#pragma unroll
            for (int ni = 0; ni < 4; ni++) {
                int boff = (ks * 8 + t) * RSB + wn + ni * 8 + r;
                bH[ni][0] = BsHi[boff];
                bH[ni][1] = BsHi[boff + 4 * RSB];
                bL[ni][0] = BsLo[boff];
                bL[ni][1] = BsLo[boff + 4 * RSB];
            }
#pragma unroll
            for (int mi = 0; mi < 4; mi++) {
                int aoff = (wm + mi * 16 + r) * RSA + ks * 8 + t;
                u32 aH0 = AsHi[aoff];
                u32 aH1 = AsHi[aoff + 8 * RSA];
                u32 aH2 = AsHi[aoff + 4];
                u32 aH3 = AsHi[aoff + 8 * RSA + 4];
                u32 aL0 = AsLo[aoff];
                u32 aL1 = AsLo[aoff + 8 * RSA];
                u32 aL2 = AsLo[aoff + 4];
                u32 aL3 = AsLo[aoff + 8 * RSA + 4];
#pragma unroll
                for (int ni = 0; ni < 4; ni++) {
                    MMA_BF16(acc[mi][ni], aH0, aH1, aH2, aH3, bH[ni][0], bH[ni][1]);
                    MMA_BF16(acc[mi][ni], aH0, aH1, aH2, aH3, bL[ni][0], bL[ni][1]);
                    MMA_BF16(acc[mi][ni], aL0, aL1, aL2, aL3, bH[ni][0], bH[ni][1]);
                }
            }
        }
        __syncthreads();
    }

    // ---- epilogue ----
#pragma unroll
    for (int mi = 0; mi < 4; mi++) {
#pragma unroll
        for (int ni = 0; ni < 4; ni++) {
            int row = bm + wm + mi * 16 + r;
            int col = bn + wn + ni * 8 + t * 2;
            *(float2*)(C + (size_t)row * N + col) =
                make_float2(acc[mi][ni][0], acc[mi][ni][1]);
            *(float2*)(C + (size_t)(row + 8) * N + col) =
                make_float2(acc[mi][ni][2], acc[mi][ni][3]);
        }
    }
}

// ---------------------------------------------------------------------------
// RoPE tables + apply
// ---------------------------------------------------------------------------
__global__ void rope_tables_kernel()
{
    int s = blockIdx.x;
    int d = threadIdx.x;           // 0..63
    double invf = pow(10000.0, -(double)(2 * d) / 128.0);
    float  ang  = (float)s * (float)invf;
    g_cos[s * 64 + d] = (float)cos((double)ang);
    g_sin[s * 64 + d] = (float)sin((double)ang);
}

__global__ void rope_apply_kernel(float* __restrict__ x, int nheads)
{
    int idx = blockIdx.x * 256 + threadIdx.x;
    int total = S_LEN * nheads * 64;
    if (idx >= total) return;
    int d = idx & 63;
    int t = idx >> 6;
    int h = t % nheads;
    int s = t / nheads;
    float c  = g_cos[s * 64 + d];
    float sn = g_sin[s * 64 + d];
    float* p = x + ((size_t)s * nheads + h) * HD;
    float x0 = p[d];
    float x1 = p[d + 64];
    p[d]      = x0 * c - x1 * sn;
    p[d + 64] = x1 * c + x0 * sn;
}

// ---------------------------------------------------------------------------
// Flash attention with analytic sliding-window causal mask (fp32).
// ---------------------------------------------------------------------------
#define ATT_SMEM_FLOATS (128*68 + 128*68 + 64*132 + 64*68 + 3*64)

__global__ __launch_bounds__(256) void attn_kernel(
    const float* __restrict__ q, const float* __restrict__ k,
    const float* __restrict__ v, float* __restrict__ o)
{
    extern __shared__ float sm[];
    float* Qs   = sm;                 // [128][68] d-major
    float* Ks   = Qs + 128 * 68;      // [128][68] d-major
    float* Vs   = Ks + 128 * 68;      // [64][132] j-major
    float* Ss   = Vs + 64 * 132;      // [64][68]  i-major
    float* mrow = Ss + 64 * 68;
    float* lrow = mrow + 64;
    float* frow = lrow + 64;

    const int tid = threadIdx.x;
    const int q0  = blockIdx.x * 64;
    const int h   = blockIdx.y;
    const int hk  = h >> 2;
    const int ty  = tid >> 4;
    const int tx  = tid & 15;

#pragma unroll
    for (int it = 0; it < 8; it++) {
        int e   = tid + 256 * it;
        int row = e >> 5;
        int dq  = (e & 31) << 2;
        float4 qq = *(const float4*)(q + ((size_t)(q0 + row) * NH + h) * HD + dq);
        Qs[(dq + 0) * 68 + row] = qq.x;
        Qs[(dq + 1) * 68 + row] = qq.y;
        Qs[(dq + 2) * 68 + row] = qq.z;
        Qs[(dq + 3) * 68 + row] = qq.w;
    }
    if (tid < 64) { mrow[tid] = -1e30f; lrow[tid] = 0.f; }

    float acc[4][8];
#pragma unroll
    for (int m = 0; m < 4; m++)
#pragma unroll
        for (int n = 0; n < 8; n++) acc[m][n] = 0.f;

    int lo = q0 - (WINDOW - 1);
    if (lo < 0) lo = 0;
    const int jt_lo = lo >> 6;
    const int jt_hi = q0 >> 6;

    for (int jt = jt_lo; jt <= jt_hi; jt++) {
        const int j0 = jt << 6;
        __syncthreads();

#pragma unroll
        for (int it = 0; it < 8; it++) {
            int e   = tid + 256 * it;
            int row = e >> 5;
            int dq  = (e & 31) << 2;
            size_t gbase = ((size_t)(j0 + row) * NKV + hk) * HD + dq;
            float4 kk4 = *(const float4*)(k + gbase);
            Ks[(dq + 0) * 68 + row] = kk4.x;
            Ks[(dq + 1) * 68 + row] = kk4.y;
            Ks[(dq + 2) * 68 + row] = kk4.z;
            Ks[(dq + 3) * 68 + row] = kk4.w;
            *(float4*)(Vs + row * 132 + dq) = *(const float4*)(v + gbase);
        }
        __syncthreads();

        float s[4][4];
#pragma unroll
        for (int m = 0; m < 4; m++)
#pragma unroll
            for (int n = 0; n < 4; n++) s[m][n] = 0.f;

#pragma unroll 4
        for (int d = 0; d < 128; d++) {
            float4 a = *(const float4*)(Qs + d * 68 + ty * 4);
            float4 b = *(const float4*)(Ks + d * 68 + tx * 4);
            s[0][0] += a.x * b.x; s[0][1] += a.x * b.y; s[0][2] += a.x * b.z; s[0][3] += a.x * b.w;
            s[1][0] += a.y * b.x; s[1][1] += a.y * b.y; s[1][2] += a.y * b.z; s[1][3] += a.y * b.w;
            s[2][0] += a.z * b.x; s[2][1] += a.z * b.y; s[2][2] += a.z * b.z; s[2][3] += a.z * b.w;
            s[3][0] += a.w * b.x; s[3][1] += a.w * b.y; s[3][2] += a.w * b.z; s[3][3] += a.w * b.w;
        }
#pragma unroll
        for (int m = 0; m < 4; m++) {
            int gi = q0 + ty * 4 + m;
#pragma unroll
            for (int n = 0; n < 4; n++) {
                int gj = j0 + tx * 4 + n;
                bool allowed = (gj <= gi) && (gj > gi - WINDOW);
                Ss[(ty * 4 + m) * 68 + tx * 4 + n] =
                    allowed ? s[m][n] * SCALE_F : -1e9f;
            }
        }
        __syncthreads();

        {
            int rr   = tid >> 2;
            int part = tid & 3;
            float* srow = Ss + rr * 68 + part * 16;
            float mx = -1e30f;
#pragma unroll
            for (int jj = 0; jj < 16; jj++) mx = fmaxf(mx, srow[jj]);
            mx = fmaxf(mx, __shfl_xor_sync(0xffffffffu, mx, 1));
            mx = fmaxf(mx, __shfl_xor_sync(0xffffffffu, mx, 2));
            float mold = mrow[rr];
            float mnew = fmaxf(mold, mx);
            float sum = 0.f;
#pragma unroll
            for (int jj = 0; jj < 16; jj++) {
                float vv = srow[jj];
                float p  = (vv > -1e8f) ? expf(vv - mnew) : 0.f;
                srow[jj] = p;
                sum += p;
            }
            sum += __shfl_xor_sync(0xffffffffu, sum, 1);
            sum += __shfl_xor_sync(0xffffffffu, sum, 2);
            if (part == 0) {
                float f = expf(mold - mnew);
                lrow[rr] = lrow[rr] * f + sum;
                mrow[rr] = mnew;
                frow[rr] = f;
            }
        }
        __syncthreads();

#pragma unroll
        for (int m = 0; m < 4; m++) {
            float f = frow[ty * 4 + m];
#pragma unroll
            for (int n = 0; n < 8; n++) acc[m][n] *= f;
        }
#pragma unroll 2
        for (int j = 0; j < 64; j++) {
            float4 b0 = *(const float4*)(Vs + j * 132 + tx * 8);
            float4 b1 = *(const float4*)(Vs + j * 132 + tx * 8 + 4);
#pragma unroll
            for (int m = 0; m < 4; m++) {
                float p = Ss[(ty * 4 + m) * 68 + j];
                acc[m][0] += p * b0.x; acc[m][1] += p * b0.y;
                acc[m][2] += p * b0.z; acc[m][3] += p * b0.w;
                acc[m][4] += p * b1.x; acc[m][5] += p * b1.y;
                acc[m][6] += p * b1.z; acc[m][7] += p * b1.w;
            }
        }
    }

#pragma unroll
    for (int m = 0; m < 4; m++) {
        float inv = 1.0f / lrow[ty * 4 + m];
        size_t base = ((size_t)(q0 + ty * 4 + m) * NH + h) * HD + tx * 8;
        float4 o0 = make_float4(acc[m][0] * inv, acc[m][1] * inv,
                                acc[m][2] * inv, acc[m][3] * inv);
        float4 o1 = make_float4(acc[m][4] * inv, acc[m][5] * inv,
                                acc[m][6] * inv, acc[m][7] * inv);
        *(float4*)(o + base)     = o0;
        *(float4*)(o + base + 4) = o1;
    }
}

// ---------------------------------------------------------------------------
// kernel_launch
// Inputs: 0=hidden_states 1=attention_mask(analytic) 2=position_ids(arange)
//         3=Wq 4=Wk 5=Wv 6=Wo
// ---------------------------------------------------------------------------
extern "C" void kernel_launch(void* const* d_in, const int* in_sizes, int n_in,
                              void* d_out, int out_size)
{
    (void)in_sizes; (void)n_in; (void)out_size;
    const float* hs = (const float*)d_in[0];
    const float* Wq = (const float*)d_in[3];
    const float* Wk = (const float*)d_in[4];
    const float* Wv = (const float*)d_in[5];
    const float* Wo = (const float*)d_in[6];
    float* out = (float*)d_out;

    float *q, *k, *v, *att;
    cudaGetSymbolAddress((void**)&q,   g_q);
    cudaGetSymbolAddress((void**)&k,   g_k);
    cudaGetSymbolAddress((void**)&v,   g_v);
    cudaGetSymbolAddress((void**)&att, g_att);

    // Q/K/V projections (tensor cores, bf16x3)
    gemm_bf16x3<<<dim3(HID / 128, S_LEN / 128), 256>>>(hs, Wq, q, S_LEN, HID,      HID);
    gemm_bf16x3<<<dim3((NKV*HD) / 128, S_LEN / 128), 256>>>(hs, Wk, k, S_LEN, NKV*HD, HID);
    gemm_bf16x3<<<dim3((NKV*HD) / 128, S_LEN / 128), 256>>>(hs, Wv, v, S_LEN, NKV*HD, HID);

    // RoPE
    rope_tables_kernel<<<S_LEN, 64>>>();
    rope_apply_kernel<<<(S_LEN * NH  * 64 + 255) / 256, 256>>>(q, NH);
    rope_apply_kernel<<<(S_LEN * NKV * 64 + 255) / 256, 256>>>(k, NKV);

    // Attention (fp32 flash, analytic sliding-window mask)
    const int att_smem = ATT_SMEM_FLOATS * (int)sizeof(float);
    cudaFuncSetAttribute(attn_kernel,
                         cudaFuncAttributeMaxDynamicSharedMemorySize, att_smem);
    attn_kernel<<<dim3(S_LEN / 64, NH), 256, att_smem>>>(q, k, v, att);

    // Output projection
    gemm_bf16x3<<<dim3(HID / 128, S_LEN / 128), 256>>>(att, Wo, out, S_LEN, HID, HID);
}

// round 4
// speedup vs baseline: 2.2540x; 1.3805x over previous
#include <cuda_runtime.h>
#include <cuda_bf16.h>
#include <stdint.h>
#include <math.h>

typedef unsigned int u32;

// Problem constants (fixed by setup_inputs)
#define S_LEN   2048
#define HID     4096
#define NH      32
#define NKV     8
#define HD      128
#define WINDOW  1024
#define SCALE_F 0.08838834764831845f   // 1/sqrt(128)

// ---------------------------------------------------------------------------
// Scratch (device globals — no allocation allowed)
// ---------------------------------------------------------------------------
__device__ float g_q  [S_LEN * NH  * HD];   // fp32 Q from proj (pre-rope)
__device__ float g_k  [S_LEN * NKV * HD];
__device__ float g_v  [S_LEN * NKV * HD];
__device__ float g_att[S_LEN * NH  * HD];
__device__ float g_cos[S_LEN * (HD / 2)];
__device__ float g_sin[S_LEN * (HD / 2)];

// bf16 hi/lo split operands for tensor-core attention
__device__ __nv_bfloat16 g_qhi[S_LEN * NH  * HD];
__device__ __nv_bfloat16 g_qlo[S_LEN * NH  * HD];
__device__ __nv_bfloat16 g_khi[S_LEN * NKV * HD];
__device__ __nv_bfloat16 g_klo[S_LEN * NKV * HD];
__device__ __nv_bfloat16 g_vthi[NKV * HD * S_LEN];   // [hk][d][s]
__device__ __nv_bfloat16 g_vtlo[NKV * HD * S_LEN];

// ---------------------------------------------------------------------------
// Common helpers
// ---------------------------------------------------------------------------
__device__ __forceinline__ u32 pack_bf16(float e0, float e1) {
    __nv_bfloat162 p = __floats2bfloat162_rn(e0, e1);   // .x = e0 (low half)
    return *reinterpret_cast<u32*>(&p);
}

#define MMA_BF16(d, a0, a1, a2, a3, b0, b1)                                 \
    asm volatile(                                                           \
        "mma.sync.aligned.m16n8k16.row.col.f32.bf16.bf16.f32 "              \
        "{%0,%1,%2,%3}, {%4,%5,%6,%7}, {%8,%9}, {%0,%1,%2,%3};"             \
        : "+f"(d[0]), "+f"(d[1]), "+f"(d[2]), "+f"(d[3])                    \
        : "r"(a0), "r"(a1), "r"(a2), "r"(a3), "r"(b0), "r"(b1))

// ---------------------------------------------------------------------------
// bf16x3 tensor-core GEMM (unchanged from R3): C = A @ B, fp32 in/out.
// ---------------------------------------------------------------------------
#define RSA 20
#define RSB 136

__global__ __launch_bounds__(256, 2) void gemm_bf16x3(
    const float* __restrict__ A, const float* __restrict__ B,
    float* __restrict__ C, int M, int N, int K)
{
    __shared__ u32 AsHi[128 * RSA];
    __shared__ u32 AsLo[128 * RSA];
    __shared__ u32 BsHi[16 * RSB];
    __shared__ u32 BsLo[16 * RSB];

    const int tid  = threadIdx.x;
    const int warp = tid >> 5;
    const int lane = tid & 31;
    const int wm   = (warp >> 2) * 64;
    const int wn   = (warp & 3)  * 32;
    const int bm   = blockIdx.y * 128;
    const int bn   = blockIdx.x * 128;

    const int r = lane >> 2;
    const int t = lane & 3;

    float acc[4][4][4];
#pragma unroll
    for (int mi = 0; mi < 4; mi++)
#pragma unroll
        for (int ni = 0; ni < 4; ni++)
#pragma unroll
            for (int c = 0; c < 4; c++) acc[mi][ni][c] = 0.f;

    const int b_kp = tid >> 4;
    const int b_n0 = (tid & 15) * 8;

    for (int k0 = 0; k0 < K; k0 += 32) {
#pragma unroll
        for (int i = 0; i < 4; i++) {
            int e   = tid + 256 * i;
            int row = e >> 3;
            int c4  = e & 7;
            float4 v = *(const float4*)(A + (size_t)(bm + row) * K + k0 + c4 * 4);
            float hx = __bfloat162float(__float2bfloat16_rn(v.x));
            float hy = __bfloat162float(__float2bfloat16_rn(v.y));
            float hz = __bfloat162float(__float2bfloat16_rn(v.z));
            float hw = __bfloat162float(__float2bfloat16_rn(v.w));
            uint2 hi = make_uint2(pack_bf16(hx, hy), pack_bf16(hz, hw));
            uint2 lo = make_uint2(pack_bf16(v.x - hx, v.y - hy),
                                  pack_bf16(v.z - hz, v.w - hw));
            *(uint2*)&AsHi[row * RSA + c4 * 2] = hi;
            *(uint2*)&AsLo[row * RSA + c4 * 2] = lo;
        }
        {
            const float* B0 = B + (size_t)(k0 + b_kp * 2) * N + bn + b_n0;
            const float* B1 = B0 + N;
            float4 u0 = *(const float4*)(B0);
            float4 u1 = *(const float4*)(B0 + 4);
            float4 w0 = *(const float4*)(B1);
            float4 w1 = *(const float4*)(B1 + 4);
            float ue[8] = {u0.x,u0.y,u0.z,u0.w,u1.x,u1.y,u1.z,u1.w};
            float we[8] = {w0.x,w0.y,w0.z,w0.w,w1.x,w1.y,w1.z,w1.w};
            u32 hiw[8], low[8];
#pragma unroll
            for (int j = 0; j < 8; j++) {
                float hu  = __bfloat162float(__float2bfloat16_rn(ue[j]));
                float hw2 = __bfloat162float(__float2bfloat16_rn(we[j]));
                hiw[j] = pack_bf16(hu, hw2);
                low[j] = pack_bf16(ue[j] - hu, we[j] - hw2);
            }
            u32* dh = &BsHi[b_kp * RSB + b_n0];
            u32* dl = &BsLo[b_kp * RSB + b_n0];
            *(uint4*)(dh)     = make_uint4(hiw[0], hiw[1], hiw[2], hiw[3]);
            *(uint4*)(dh + 4) = make_uint4(hiw[4], hiw[5], hiw[6], hiw[7]);
            *(uint4*)(dl)     = make_uint4(low[0], low[1], low[2], low[3]);
            *(uint4*)(dl + 4) = make_uint4(low[4], low[5], low[6], low[7]);
        }
        __syncthreads();

#pragma unroll
        for (int ks = 0; ks < 2; ks++) {
            u32 bH[4][2], bL[4][2];
#pragma unroll
            for (int ni = 0; ni < 4; ni++) {
                int boff = (ks * 8 + t) * RSB + wn + ni * 8 + r;
                bH[ni][0] = BsHi[boff];
                bH[ni][1] = BsHi[boff + 4 * RSB];
                bL[ni][0] = BsLo[boff];
                bL[ni][1] = BsLo[boff + 4 * RSB];
            }
#pragma unroll
            for (int mi = 0; mi < 4; mi++) {
                int aoff = (wm + mi * 16 + r) * RSA + ks * 8 + t;
                u32 aH0 = AsHi[aoff];
                u32 aH1 = AsHi[aoff + 8 * RSA];
                u32 aH2 = AsHi[aoff + 4];
                u32 aH3 = AsHi[aoff + 8 * RSA + 4];
                u32 aL0 = AsLo[aoff];
                u32 aL1 = AsLo[aoff + 8 * RSA];
                u32 aL2 = AsLo[aoff + 4];
                u32 aL3 = AsLo[aoff + 8 * RSA + 4];
#pragma unroll
                for (int ni = 0; ni < 4; ni++) {
                    MMA_BF16(acc[mi][ni], aH0, aH1, aH2, aH3, bH[ni][0], bH[ni][1]);
                    MMA_BF16(acc[mi][ni], aH0, aH1, aH2, aH3, bL[ni][0], bL[ni][1]);
                    MMA_BF16(acc[mi][ni], aL0, aL1, aL2, aL3, bH[ni][0], bH[ni][1]);
                }
            }
        }
        __syncthreads();
    }

#pragma unroll
    for (int mi = 0; mi < 4; mi++) {
#pragma unroll
        for (int ni = 0; ni < 4; ni++) {
            int row = bm + wm + mi * 16 + r;
            int col = bn + wn + ni * 8 + t * 2;
            *(float2*)(C + (size_t)row * N + col) =
                make_float2(acc[mi][ni][0], acc[mi][ni][1]);
            *(float2*)(C + (size_t)(row + 8) * N + col) =
                make_float2(acc[mi][ni][2], acc[mi][ni][3]);
        }
    }
}

// ---------------------------------------------------------------------------
// RoPE tables; RoPE apply now emits bf16 hi/lo split arrays.
// ---------------------------------------------------------------------------
__global__ void rope_tables_kernel()
{
    int s = blockIdx.x;
    int d = threadIdx.x;           // 0..63
    double invf = pow(10000.0, -(double)(2 * d) / 128.0);
    float  ang  = (float)s * (float)invf;
    g_cos[s * 64 + d] = (float)cos((double)ang);
    g_sin[s * 64 + d] = (float)sin((double)ang);
}

__global__ void rope_split_kernel(const float* __restrict__ x,
                                  __nv_bfloat16* __restrict__ xhi,
                                  __nv_bfloat16* __restrict__ xlo,
                                  int nheads)
{
    int idx = blockIdx.x * 256 + threadIdx.x;
    int total = S_LEN * nheads * 64;
    if (idx >= total) return;
    int d = idx & 63;
    int t = idx >> 6;
    int h = t % nheads;
    int s = t / nheads;
    float c  = g_cos[s * 64 + d];
    float sn = g_sin[s * 64 + d];
    size_t base = ((size_t)s * nheads + h) * HD;
    float x0 = x[base + d];
    float x1 = x[base + d + 64];
    float r0 = x0 * c - x1 * sn;
    float r1 = x1 * c + x0 * sn;
    float h0 = __bfloat162float(__float2bfloat16_rn(r0));
    float h1 = __bfloat162float(__float2bfloat16_rn(r1));
    xhi[base + d]      = __float2bfloat16_rn(h0);
    xhi[base + d + 64] = __float2bfloat16_rn(h1);
    xlo[base + d]      = __float2bfloat16_rn(r0 - h0);
    xlo[base + d + 64] = __float2bfloat16_rn(r1 - h1);
}

// ---------------------------------------------------------------------------
// V split + transpose: g_v [s][hk][d] fp32 -> g_vt{hi,lo} [hk][d][s] bf16.
// 32x32 tiles via smem. Grid: (S/32, HD/32, NKV), block 32x8.
// ---------------------------------------------------------------------------
__global__ __launch_bounds__(256) void v_split_transpose_kernel()
{
    __shared__ float tile[32][33];
    const int s0 = blockIdx.x * 32;
    const int d0 = blockIdx.y * 32;
    const int hk = blockIdx.z;
    const int tx = threadIdx.x;    // 0..31
    const int ty = threadIdx.y;    // 0..7

#pragma unroll
    for (int i = 0; i < 4; i++) {
        int s = s0 + ty + i * 8;
        tile[ty + i * 8][tx] = g_v[((size_t)s * NKV + hk) * HD + d0 + tx];
    }
    __syncthreads();
#pragma unroll
    for (int i = 0; i < 4; i++) {
        int d = d0 + ty + i * 8;
        float val = tile[tx][ty + i * 8];
        float hi  = __bfloat162float(__float2bfloat16_rn(val));
        size_t o  = ((size_t)hk * HD + d) * S_LEN + s0 + tx;
        g_vthi[o] = __float2bfloat16_rn(hi);
        g_vtlo[o] = __float2bfloat16_rn(val - hi);
    }
}

// ---------------------------------------------------------------------------
// Tensor-core flash attention, bf16x3, analytic sliding-window mask.
// Block: 64 q-rows x 1 head, 128 threads (4 warps, 16 rows each).
// Smem pair-word layouts (u32 = 2 bf16 along k):
//   Q,K: [row][dpair]  stride 68  (64 data + 4 pad)
//   V:   [d][jpair]    stride 36  (32 data + 4 pad)
// ---------------------------------------------------------------------------
#define RSQ 68
#define RSV 36
#define SM_QHI 0
#define SM_QLO (64 * RSQ)
#define SM_KHI (2 * 64 * RSQ)
#define SM_KLO (3 * 64 * RSQ)
#define SM_VHI (4 * 64 * RSQ)
#define SM_VLO (4 * 64 * RSQ + 128 * RSV)
#define ATT_SMEM_WORDS (4 * 64 * RSQ + 2 * 128 * RSV)

__global__ __launch_bounds__(128) void attn_mma_kernel(
    const __nv_bfloat16* __restrict__ qhi, const __nv_bfloat16* __restrict__ qlo,
    const __nv_bfloat16* __restrict__ khi, const __nv_bfloat16* __restrict__ klo,
    const __nv_bfloat16* __restrict__ vthi, const __nv_bfloat16* __restrict__ vtlo,
    float* __restrict__ o)
{
    extern __shared__ u32 sm[];
    u32* Qhi = sm + SM_QHI;
    u32* Qlo = sm + SM_QLO;
    u32* Khi = sm + SM_KHI;
    u32* Klo = sm + SM_KLO;
    u32* Vhi = sm + SM_VHI;
    u32* Vlo = sm + SM_VLO;

    const int tid  = threadIdx.x;
    const int warp = tid >> 5;
    const int lane = tid & 31;
    const int g    = lane >> 2;     // 0..7  fragment row group
    const int t4   = lane & 3;      // 0..3  fragment k-pair group
    const int q0   = blockIdx.x * 64;
    const int h    = blockIdx.y;
    const int hk   = h >> 2;
    const int wrow = warp * 16;

    const float NEGINF = __int_as_float(0xff800000);

    // ---- load Q tile (64 rows x 128 d, hi/lo) ----
#pragma unroll
    for (int it = 0; it < 8; it++) {
        int e   = tid + 128 * it;      // 0..1023 uint4 slots
        int row = e >> 4;
        int c   = e & 15;
        size_t gb = ((size_t)(q0 + row) * NH + h) * HD + c * 8;
        *(uint4*)&Qhi[row * RSQ + c * 4] = *(const uint4*)(qhi + gb);
        *(uint4*)&Qlo[row * RSQ + c * 4] = *(const uint4*)(qlo + gb);
    }

    const int i0 = q0 + wrow + g;      // thread's first row
    const int i1 = i0 + 8;             // thread's second row

    float oacc[16][4];
#pragma unroll
    for (int n = 0; n < 16; n++)
#pragma unroll
        for (int c = 0; c < 4; c++) oacc[n][c] = 0.f;
    float m0 = -1e30f, m1 = -1e30f, l0 = 0.f, l1 = 0.f;

    int lo_j = q0 - (WINDOW - 1);
    if (lo_j < 0) lo_j = 0;
    const int jt_lo = lo_j >> 6;
    const int jt_hi = q0 >> 6;

    for (int jt = jt_lo; jt <= jt_hi; jt++) {
        const int j0 = jt << 6;
        __syncthreads();
        // ---- load K (hi/lo) and V (hi/lo) tiles ----
#pragma unroll
        for (int it = 0; it < 8; it++) {
            int e = tid + 128 * it;
            {   // K: 64 rows x 16 uint4
                int row = e >> 4, c = e & 15;
                size_t gb = ((size_t)(j0 + row) * NKV + hk) * HD + c * 8;
                *(uint4*)&Khi[row * RSQ + c * 4] = *(const uint4*)(khi + gb);
                *(uint4*)&Klo[row * RSQ + c * 4] = *(const uint4*)(klo + gb);
            }
            {   // V: 128 rows(d) x 8 uint4 (64 j)
                int d = e >> 3, c = e & 7;
                size_t gb = ((size_t)hk * HD + d) * S_LEN + j0 + c * 8;
                *(uint4*)&Vhi[d * RSV + c * 4] = *(const uint4*)(vthi + gb);
                *(uint4*)&Vlo[d * RSV + c * 4] = *(const uint4*)(vtlo + gb);
            }
        }
        __syncthreads();

        // ---- S = Q K^T (bf16x3) ----
        float sacc[8][4];
#pragma unroll
        for (int n = 0; n < 8; n++)
#pragma unroll
            for (int c = 0; c < 4; c++) sacc[n][c] = 0.f;

#pragma unroll
        for (int kt = 0; kt < 8; kt++) {
            int ao = (wrow + g) * RSQ + kt * 8 + t4;
            u32 qh0 = Qhi[ao];
            u32 qh1 = Qhi[ao + 8 * RSQ];
            u32 qh2 = Qhi[ao + 4];
            u32 qh3 = Qhi[ao + 8 * RSQ + 4];
            u32 ql0 = Qlo[ao];
            u32 ql1 = Qlo[ao + 8 * RSQ];
            u32 ql2 = Qlo[ao + 4];
            u32 ql3 = Qlo[ao + 8 * RSQ + 4];
#pragma unroll
            for (int nt = 0; nt < 8; nt++) {
                int bo = (nt * 8 + g) * RSQ + kt * 8 + t4;
                u32 bh0 = Khi[bo], bh1 = Khi[bo + 4];
                u32 bl0 = Klo[bo], bl1 = Klo[bo + 4];
                MMA_BF16(sacc[nt], qh0, qh1, qh2, qh3, bh0, bh1);
                MMA_BF16(sacc[nt], qh0, qh1, qh2, qh3, bl0, bl1);
                MMA_BF16(sacc[nt], ql0, ql1, ql2, ql3, bh0, bh1);
            }
        }

        // ---- scale + mask ----
        bool full = (j0 + 63 <= q0 + wrow) && (j0 > q0 + wrow + 15 - WINDOW);
        if (full) {
#pragma unroll
            for (int nt = 0; nt < 8; nt++)
#pragma unroll
                for (int c = 0; c < 4; c++) sacc[nt][c] *= SCALE_F;
        } else {
#pragma unroll
            for (int nt = 0; nt < 8; nt++) {
                int jb = j0 + nt * 8 + 2 * t4;
                bool a00 = (jb     <= i0) && (jb     > i0 - WINDOW);
                bool a01 = (jb + 1 <= i0) && (jb + 1 > i0 - WINDOW);
                bool a10 = (jb     <= i1) && (jb     > i1 - WINDOW);
                bool a11 = (jb + 1 <= i1) && (jb + 1 > i1 - WINDOW);
                sacc[nt][0] = a00 ? sacc[nt][0] * SCALE_F : NEGINF;
                sacc[nt][1] = a01 ? sacc[nt][1] * SCALE_F : NEGINF;
                sacc[nt][2] = a10 ? sacc[nt][2] * SCALE_F : NEGINF;
                sacc[nt][3] = a11 ? sacc[nt][3] * SCALE_F : NEGINF;
            }
        }

        // ---- online softmax (rows i0, i1) ----
        float mx0 = -1e30f, mx1 = -1e30f;
#pragma unroll
        for (int nt = 0; nt < 8; nt++) {
            mx0 = fmaxf(mx0, fmaxf(sacc[nt][0], sacc[nt][1]));
            mx1 = fmaxf(mx1, fmaxf(sacc[nt][2], sacc[nt][3]));
        }
        mx0 = fmaxf(mx0, __shfl_xor_sync(0xffffffffu, mx0, 1));
        mx0 = fmaxf(mx0, __shfl_xor_sync(0xffffffffu, mx0, 2));
        mx1 = fmaxf(mx1, __shfl_xor_sync(0xffffffffu, mx1, 1));
        mx1 = fmaxf(mx1, __shfl_xor_sync(0xffffffffu, mx1, 2));
        float mn0 = fmaxf(m0, mx0);
        float mn1 = fmaxf(m1, mx1);
        float f0 = __expf(m0 - mn0);
        float f1 = __expf(m1 - mn1);
        float sum0 = 0.f, sum1 = 0.f;
#pragma unroll
        for (int nt = 0; nt < 8; nt++) {
            sacc[nt][0] = __expf(sacc[nt][0] - mn0); sum0 += sacc[nt][0];
            sacc[nt][1] = __expf(sacc[nt][1] - mn0); sum0 += sacc[nt][1];
            sacc[nt][2] = __expf(sacc[nt][2] - mn1); sum1 += sacc[nt][2];
            sacc[nt][3] = __expf(sacc[nt][3] - mn1); sum1 += sacc[nt][3];
        }
        sum0 += __shfl_xor_sync(0xffffffffu, sum0, 1);
        sum0 += __shfl_xor_sync(0xffffffffu, sum0, 2);
        sum1 += __shfl_xor_sync(0xffffffffu, sum1, 1);
        sum1 += __shfl_xor_sync(0xffffffffu, sum1, 2);
        l0 = l0 * f0 + sum0;  m0 = mn0;
        l1 = l1 * f1 + sum1;  m1 = mn1;

        // ---- rescale O accumulators ----
#pragma unroll
        for (int n = 0; n < 16; n++) {
            oacc[n][0] *= f0; oacc[n][1] *= f0;
            oacc[n][2] *= f1; oacc[n][3] *= f1;
        }

        // ---- O += P V (bf16x3; P fragments straight from sacc) ----
#pragma unroll
        for (int kt = 0; kt < 4; kt++) {
            float p00 = sacc[2*kt][0],   p01 = sacc[2*kt][1];
            float p02 = sacc[2*kt][2],   p03 = sacc[2*kt][3];
            float p10 = sacc[2*kt+1][0], p11 = sacc[2*kt+1][1];
            float p12 = sacc[2*kt+1][2], p13 = sacc[2*kt+1][3];
            float h00 = __bfloat162float(__float2bfloat16_rn(p00));
            float h01 = __bfloat162float(__float2bfloat16_rn(p01));
            float h02 = __bfloat162float(__float2bfloat16_rn(p02));
            float h03 = __bfloat162float(__float2bfloat16_rn(p03));
            float h10 = __bfloat162float(__float2bfloat16_rn(p10));
            float h11 = __bfloat162float(__float2bfloat16_rn(p11));
            float h12 = __bfloat162float(__float2bfloat16_rn(p12));
            float h13 = __bfloat162float(__float2bfloat16_rn(p13));
            u32 ah0 = pack_bf16(h00, h01);
            u32 ah1 = pack_bf16(h02, h03);
            u32 ah2 = pack_bf16(h10, h11);
            u32 ah3 = pack_bf16(h12, h13);
            u32 al0 = pack_bf16(p00 - h00, p01 - h01);
            u32 al1 = pack_bf16(p02 - h02, p03 - h03);
            u32 al2 = pack_bf16(p10 - h10, p11 - h11);
            u32 al3 = pack_bf16(p12 - h12, p13 - h13);
#pragma unroll
            for (int nt = 0; nt < 16; nt++) {
                int vo = (nt * 8 + g) * RSV + kt * 8 + t4;
                u32 vh0 = Vhi[vo], vh1 = Vhi[vo + 4];
                u32 vl0 = Vlo[vo], vl1 = Vlo[vo + 4];
                MMA_BF16(oacc[nt], ah0, ah1, ah2, ah3, vh0, vh1);
                MMA_BF16(oacc[nt], ah0, ah1, ah2, ah3, vl0, vl1);
                MMA_BF16(oacc[nt], al0, al1, al2, al3, vh0, vh1);
            }
        }
    }

    // ---- epilogue ----
    float inv0 = 1.0f / l0;
    float inv1 = 1.0f / l1;
#pragma unroll
    for (int nt = 0; nt < 16; nt++) {
        int col = nt * 8 + 2 * t4;
        size_t b0 = ((size_t)i0 * NH + h) * HD + col;
        size_t b1 = ((size_t)i1 * NH + h) * HD + col;
        *(float2*)(o + b0) = make_float2(oacc[nt][0] * inv0, oacc[nt][1] * inv0);
        *(float2*)(o + b1) = make_float2(oacc[nt][2] * inv1, oacc[nt][3] * inv1);
    }
}

// ---------------------------------------------------------------------------
// kernel_launch
// Inputs: 0=hidden_states 1=attention_mask(analytic) 2=position_ids(arange)
//         3=Wq 4=Wk 5=Wv 6=Wo
// ---------------------------------------------------------------------------
extern "C" void kernel_launch(void* const* d_in, const int* in_sizes, int n_in,
                              void* d_out, int out_size)
{
    (void)in_sizes; (void)n_in; (void)out_size;
    const float* hs = (const float*)d_in[0];
    const float* Wq = (const float*)d_in[3];
    const float* Wk = (const float*)d_in[4];
    const float* Wv = (const float*)d_in[5];
    const float* Wo = (const float*)d_in[6];
    float* out = (float*)d_out;

    float *q, *k, *att;
    __nv_bfloat16 *qhi, *qlo, *khi, *klo, *vthi, *vtlo;
    float* v;
    cudaGetSymbolAddress((void**)&q,    g_q);
    cudaGetSymbolAddress((void**)&k,    g_k);
    cudaGetSymbolAddress((void**)&v,    g_v);
    cudaGetSymbolAddress((void**)&att,  g_att);
    cudaGetSymbolAddress((void**)&qhi,  g_qhi);
    cudaGetSymbolAddress((void**)&qlo,  g_qlo);
    cudaGetSymbolAddress((void**)&khi,  g_khi);
    cudaGetSymbolAddress((void**)&klo,  g_klo);
    cudaGetSymbolAddress((void**)&vthi, g_vthi);
    cudaGetSymbolAddress((void**)&vtlo, g_vtlo);

    // Q/K/V projections (tensor cores, bf16x3)
    gemm_bf16x3<<<dim3(HID / 128, S_LEN / 128), 256>>>(hs, Wq, q, S_LEN, HID,      HID);
    gemm_bf16x3<<<dim3((NKV*HD) / 128, S_LEN / 128), 256>>>(hs, Wk, k, S_LEN, NKV*HD, HID);
    gemm_bf16x3<<<dim3((NKV*HD) / 128, S_LEN / 128), 256>>>(hs, Wv, v, S_LEN, NKV*HD, HID);

    // RoPE + hi/lo split; V split+transpose
    rope_tables_kernel<<<S_LEN, 64>>>();
    rope_split_kernel<<<(S_LEN * NH  * 64 + 255) / 256, 256>>>(q, qhi, qlo, NH);
    rope_split_kernel<<<(S_LEN * NKV * 64 + 255) / 256, 256>>>(k, khi, klo, NKV);
    v_split_transpose_kernel<<<dim3(S_LEN / 32, HD / 32, NKV), dim3(32, 8)>>>();

    // Attention (tensor cores, bf16x3, analytic sliding-window mask)
    const int att_smem = ATT_SMEM_WORDS * (int)sizeof(u32);
    cudaFuncSetAttribute(attn_mma_kernel,
                         cudaFuncAttributeMaxDynamicSharedMemorySize, att_smem);
    attn_mma_kernel<<<dim3(S_LEN / 64, NH), 128, att_smem>>>(
        qhi, qlo, khi, klo, vthi, vtlo, att);

    // Output projection
    gemm_bf16x3<<<dim3(HID / 128, S_LEN / 128), 256>>>(att, Wo, out, S_LEN, HID, HID);
}

// round 5
// speedup vs baseline: 2.6171x; 1.1611x over previous
#include <cuda_runtime.h>
#include <cuda_bf16.h>
#include <stdint.h>
#include <math.h>

typedef unsigned int u32;

#define S_LEN   2048
#define HID     4096
#define NH      32
#define NKV     8
#define HD      128
#define WINDOW  1024
#define SCALE_F 0.08838834764831845f   // 1/sqrt(128)

// ---------------------------------------------------------------------------
// Scratch (device globals)
// ---------------------------------------------------------------------------
__device__ float g_q  [S_LEN * NH  * HD];
__device__ float g_k  [S_LEN * NKV * HD];
__device__ float g_v  [S_LEN * NKV * HD];
__device__ float g_cos[S_LEN * (HD / 2)];
__device__ float g_sin[S_LEN * (HD / 2)];

// attention operands (bf16 hi/lo)
__device__ __nv_bfloat16 g_qhi[S_LEN * NH  * HD];
__device__ __nv_bfloat16 g_qlo[S_LEN * NH  * HD];
__device__ __nv_bfloat16 g_khi[S_LEN * NKV * HD];
__device__ __nv_bfloat16 g_klo[S_LEN * NKV * HD];
__device__ __nv_bfloat16 g_vthi[NKV * HD * S_LEN];   // [hk][d][s]
__device__ __nv_bfloat16 g_vtlo[NKV * HD * S_LEN];

// pre-split GEMM operands (u32 = bf16 k-pair words)
__device__ u32 g_hshi[S_LEN * HID / 2];
__device__ u32 g_hslo[S_LEN * HID / 2];
__device__ u32 g_wqhi[HID / 2 * (NH  * HD)];
__device__ u32 g_wqlo[HID / 2 * (NH  * HD)];
__device__ u32 g_wkhi[HID / 2 * (NKV * HD)];
__device__ u32 g_wklo[HID / 2 * (NKV * HD)];
__device__ u32 g_wvhi[HID / 2 * (NKV * HD)];
__device__ u32 g_wvlo[HID / 2 * (NKV * HD)];
__device__ u32 g_wohi[(NH * HD) / 2 * HID];
__device__ u32 g_wolo[(NH * HD) / 2 * HID];
__device__ u32 g_athi[S_LEN * HID / 2];   // attention output, pre-split
__device__ u32 g_atlo[S_LEN * HID / 2];

// ---------------------------------------------------------------------------
// Helpers
// ---------------------------------------------------------------------------
__device__ __forceinline__ u32 pack_bf16(float e0, float e1) {
    __nv_bfloat162 p = __floats2bfloat162_rn(e0, e1);   // .x = e0 (low half)
    return *reinterpret_cast<u32*>(&p);
}

__device__ __forceinline__ void split_pair(float a, float b, u32& hi, u32& lo) {
    float ha = __bfloat162float(__float2bfloat16_rn(a));
    float hb = __bfloat162float(__float2bfloat16_rn(b));
    hi = pack_bf16(ha, hb);
    lo = pack_bf16(a - ha, b - hb);
}

__device__ __forceinline__ void cp16(u32* dst, const u32* src) {
    u32 s = (u32)__cvta_generic_to_shared(dst);
    asm volatile("cp.async.cg.shared.global [%0], [%1], 16;" :: "r"(s), "l"(src));
}

#define MMA_BF16(d, a0, a1, a2, a3, b0, b1)                                 \
    asm volatile(                                                           \
        "mma.sync.aligned.m16n8k16.row.col.f32.bf16.bf16.f32 "              \
        "{%0,%1,%2,%3}, {%4,%5,%6,%7}, {%8,%9}, {%0,%1,%2,%3};"             \
        : "+f"(d[0]), "+f"(d[1]), "+f"(d[2]), "+f"(d[3])                    \
        : "r"(a0), "r"(a1), "r"(a2), "r"(a3), "r"(b0), "r"(b1))

// ---------------------------------------------------------------------------
// Split kernels: fp32 -> bf16 hi/lo pair-words.
// A-style: pairs along a row (k, k+1 contiguous).  total = M*K/2 words.
// ---------------------------------------------------------------------------
__global__ void split_A_kernel(const float* __restrict__ X,
                               u32* __restrict__ hi, u32* __restrict__ lo,
                               int total_words)
{
    int i = blockIdx.x * 256 + threadIdx.x;
    if (i >= total_words) return;
    float2 xy = *(const float2*)(X + (size_t)i * 2);
    split_pair(xy.x, xy.y, hi[i], lo[i]);
}

// B-style: word(kp,n) pairs W[2kp][n] with W[2kp+1][n].
__global__ void split_B_kernel(const float* __restrict__ W,
                               u32* __restrict__ hi, u32* __restrict__ lo,
                               int Kp, int N)
{
    int i = blockIdx.x * 256 + threadIdx.x;
    if (i >= Kp * N) return;
    int kp = i / N;
    int n  = i - kp * N;
    float a = W[(size_t)(2 * kp)     * N + n];
    float b = W[(size_t)(2 * kp + 1) * N + n];
    split_pair(a, b, hi[i], lo[i]);
}

// ---------------------------------------------------------------------------
// Pre-split bf16x3 GEMM with cp.async double buffering.
// C[M,N] = A[M,K] @ B[K,N]; operands given as hi/lo pair-word arrays.
// Block tile 128x128, BK=32 (16 pair rows), 256 threads, 2 stages.
// ---------------------------------------------------------------------------
#define RSA 20
#define RSB 136
#define STG_A   (128 * RSA)              // 2560 words
#define STG_B   (16 * RSB)               // 2176 words
#define STG_WORDS (2 * STG_A + 2 * STG_B)   // AsHi,AsLo,BsHi,BsLo = 9472
#define GEMM_SMEM_BYTES (2 * STG_WORDS * 4) // 75776 B

__global__ __launch_bounds__(256, 2) void gemm_pre(
    const u32* __restrict__ Ahi, const u32* __restrict__ Alo,
    const u32* __restrict__ Bhi, const u32* __restrict__ Blo,
    float* __restrict__ C, int M, int N, int Kp)
{
    extern __shared__ u32 smem[];

    const int tid  = threadIdx.x;
    const int warp = tid >> 5;
    const int lane = tid & 31;
    const int wm   = (warp >> 2) * 64;
    const int wn   = (warp & 3)  * 32;
    const int bm   = blockIdx.y * 128;
    const int bn   = blockIdx.x * 128;
    const int r = lane >> 2;
    const int t = lane & 3;

    float acc[4][4][4];
#pragma unroll
    for (int mi = 0; mi < 4; mi++)
#pragma unroll
        for (int ni = 0; ni < 4; ni++)
#pragma unroll
            for (int c = 0; c < 4; c++) acc[mi][ni][c] = 0.f;

    // loader indices: A chunks (512): row=e>>2, c=e&3 ; B chunks (512): krow=e>>5, c=e&31
    const int a_row0 = tid >> 1;           // e = tid      -> row tid>>1? no:
    (void)a_row0;

    const int KT = Kp / 16;

    auto load_stage = [&](int kt, int buf) {
        u32* base = smem + buf * STG_WORDS;
        u32* sAhi = base;
        u32* sAlo = base + STG_A;
        u32* sBhi = base + 2 * STG_A;
        u32* sBlo = base + 2 * STG_A + STG_B;
        int kp0 = kt * 16;
#pragma unroll
        for (int i = 0; i < 2; i++) {
            int e   = tid + 256 * i;       // 0..511
            int row = e >> 2;
            int c   = e & 3;
            const size_t ga = (size_t)(bm + row) * Kp + kp0 + c * 4;
            cp16(&sAhi[row * RSA + c * 4], Ahi + ga);
            cp16(&sAlo[row * RSA + c * 4], Alo + ga);
        }
#pragma unroll
        for (int i = 0; i < 2; i++) {
            int e    = tid + 256 * i;      // 0..511
            int krow = e >> 5;
            int c    = e & 31;
            const size_t gb = (size_t)(kp0 + krow) * N + bn + c * 4;
            cp16(&sBhi[krow * RSB + c * 4], Bhi + gb);
            cp16(&sBlo[krow * RSB + c * 4], Blo + gb);
        }
    };

    load_stage(0, 0);
    asm volatile("cp.async.commit_group;");

    for (int kt = 0; kt < KT; kt++) {
        if (kt + 1 < KT) {
            load_stage(kt + 1, (kt + 1) & 1);
            asm volatile("cp.async.commit_group;");
            asm volatile("cp.async.wait_group 1;");
        } else {
            asm volatile("cp.async.wait_group 0;");
        }
        __syncthreads();

        u32* base = smem + (kt & 1) * STG_WORDS;
        u32* sAhi = base;
        u32* sAlo = base + STG_A;
        u32* sBhi = base + 2 * STG_A;
        u32* sBlo = base + 2 * STG_A + STG_B;

#pragma unroll
        for (int ks = 0; ks < 2; ks++) {
            u32 bH[4][2], bL[4][2];
#pragma unroll
            for (int ni = 0; ni < 4; ni++) {
                int boff = (ks * 8 + t) * RSB + wn + ni * 8 + r;
                bH[ni][0] = sBhi[boff];
                bH[ni][1] = sBhi[boff + 4 * RSB];
                bL[ni][0] = sBlo[boff];
                bL[ni][1] = sBlo[boff + 4 * RSB];
            }
#pragma unroll
            for (int mi = 0; mi < 4; mi++) {
                int aoff = (wm + mi * 16 + r) * RSA + ks * 8 + t;
                u32 aH0 = sAhi[aoff];
                u32 aH1 = sAhi[aoff + 8 * RSA];
                u32 aH2 = sAhi[aoff + 4];
                u32 aH3 = sAhi[aoff + 8 * RSA + 4];
                u32 aL0 = sAlo[aoff];
                u32 aL1 = sAlo[aoff + 8 * RSA];
                u32 aL2 = sAlo[aoff + 4];
                u32 aL3 = sAlo[aoff + 8 * RSA + 4];
#pragma unroll
                for (int ni = 0; ni < 4; ni++) {
                    MMA_BF16(acc[mi][ni], aH0, aH1, aH2, aH3, bH[ni][0], bH[ni][1]);
                    MMA_BF16(acc[mi][ni], aH0, aH1, aH2, aH3, bL[ni][0], bL[ni][1]);
                    MMA_BF16(acc[mi][ni], aL0, aL1, aL2, aL3, bH[ni][0], bH[ni][1]);
                }
            }
        }
        __syncthreads();
    }

#pragma unroll
    for (int mi = 0; mi < 4; mi++) {
#pragma unroll
        for (int ni = 0; ni < 4; ni++) {
            int row = bm + wm + mi * 16 + r;
            int col = bn + wn + ni * 8 + t * 2;
            *(float2*)(C + (size_t)row * N + col) =
                make_float2(acc[mi][ni][0], acc[mi][ni][1]);
            *(float2*)(C + (size_t)(row + 8) * N + col) =
                make_float2(acc[mi][ni][2], acc[mi][ni][3]);
        }
    }
}

// ---------------------------------------------------------------------------
// RoPE
// ---------------------------------------------------------------------------
__global__ void rope_tables_kernel()
{
    int s = blockIdx.x;
    int d = threadIdx.x;
    double invf = pow(10000.0, -(double)(2 * d) / 128.0);
    float  ang  = (float)s * (float)invf;
    g_cos[s * 64 + d] = (float)cos((double)ang);
    g_sin[s * 64 + d] = (float)sin((double)ang);
}

__global__ void rope_split_kernel(const float* __restrict__ x,
                                  __nv_bfloat16* __restrict__ xhi,
                                  __nv_bfloat16* __restrict__ xlo,
                                  int nheads)
{
    int idx = blockIdx.x * 256 + threadIdx.x;
    int total = S_LEN * nheads * 64;
    if (idx >= total) return;
    int d = idx & 63;
    int t = idx >> 6;
    int h = t % nheads;
    int s = t / nheads;
    float c  = g_cos[s * 64 + d];
    float sn = g_sin[s * 64 + d];
    size_t base = ((size_t)s * nheads + h) * HD;
    float x0 = x[base + d];
    float x1 = x[base + d + 64];
    float r0 = x0 * c - x1 * sn;
    float r1 = x1 * c + x0 * sn;
    float h0 = __bfloat162float(__float2bfloat16_rn(r0));
    float h1 = __bfloat162float(__float2bfloat16_rn(r1));
    xhi[base + d]      = __float2bfloat16_rn(h0);
    xhi[base + d + 64] = __float2bfloat16_rn(h1);
    xlo[base + d]      = __float2bfloat16_rn(r0 - h0);
    xlo[base + d + 64] = __float2bfloat16_rn(r1 - h1);
}

// ---------------------------------------------------------------------------
// V split + transpose: g_v [s][hk][d] -> g_vt{hi,lo} [hk][d][s]
// ---------------------------------------------------------------------------
__global__ __launch_bounds__(256) void v_split_transpose_kernel()
{
    __shared__ float tile[32][33];
    const int s0 = blockIdx.x * 32;
    const int d0 = blockIdx.y * 32;
    const int hk = blockIdx.z;
    const int tx = threadIdx.x;
    const int ty = threadIdx.y;

#pragma unroll
    for (int i = 0; i < 4; i++) {
        int s = s0 + ty + i * 8;
        tile[ty + i * 8][tx] = g_v[((size_t)s * NKV + hk) * HD + d0 + tx];
    }
    __syncthreads();
#pragma unroll
    for (int i = 0; i < 4; i++) {
        int d = d0 + ty + i * 8;
        float val = tile[tx][ty + i * 8];
        float hi  = __bfloat162float(__float2bfloat16_rn(val));
        size_t o  = ((size_t)hk * HD + d) * S_LEN + s0 + tx;
        g_vthi[o] = __float2bfloat16_rn(hi);
        g_vtlo[o] = __float2bfloat16_rn(val - hi);
    }
}

// ---------------------------------------------------------------------------
// Tensor-core flash attention (bf16x3). Epilogue emits pre-split pair-words.
// ---------------------------------------------------------------------------
#define RSQ 68
#define RSV 36
#define SM_QHI 0
#define SM_QLO (64 * RSQ)
#define SM_KHI (2 * 64 * RSQ)
#define SM_KLO (3 * 64 * RSQ)
#define SM_VHI (4 * 64 * RSQ)
#define SM_VLO (4 * 64 * RSQ + 128 * RSV)
#define ATT_SMEM_WORDS (4 * 64 * RSQ + 2 * 128 * RSV)

__global__ __launch_bounds__(128) void attn_mma_kernel(
    const __nv_bfloat16* __restrict__ qhi, const __nv_bfloat16* __restrict__ qlo,
    const __nv_bfloat16* __restrict__ khi, const __nv_bfloat16* __restrict__ klo,
    const __nv_bfloat16* __restrict__ vthi, const __nv_bfloat16* __restrict__ vtlo,
    u32* __restrict__ athi, u32* __restrict__ atlo)
{
    extern __shared__ u32 sm[];
    u32* Qhi = sm + SM_QHI;
    u32* Qlo = sm + SM_QLO;
    u32* Khi = sm + SM_KHI;
    u32* Klo = sm + SM_KLO;
    u32* Vhi = sm + SM_VHI;
    u32* Vlo = sm + SM_VLO;

    const int tid  = threadIdx.x;
    const int warp = tid >> 5;
    const int lane = tid & 31;
    const int g    = lane >> 2;
    const int t4   = lane & 3;
    const int q0   = blockIdx.x * 64;
    const int h    = blockIdx.y;
    const int hk   = h >> 2;
    const int wrow = warp * 16;

    const float NEGINF = __int_as_float(0xff800000);

#pragma unroll
    for (int it = 0; it < 8; it++) {
        int e   = tid + 128 * it;
        int row = e >> 4;
        int c   = e & 15;
        size_t gb = ((size_t)(q0 + row) * NH + h) * HD + c * 8;
        *(uint4*)&Qhi[row * RSQ + c * 4] = *(const uint4*)(qhi + gb);
        *(uint4*)&Qlo[row * RSQ + c * 4] = *(const uint4*)(qlo + gb);
    }

    const int i0 = q0 + wrow + g;
    const int i1 = i0 + 8;

    float oacc[16][4];
#pragma unroll
    for (int n = 0; n < 16; n++)
#pragma unroll
        for (int c = 0; c < 4; c++) oacc[n][c] = 0.f;
    float m0 = -1e30f, m1 = -1e30f, l0 = 0.f, l1 = 0.f;

    int lo_j = q0 - (WINDOW - 1);
    if (lo_j < 0) lo_j = 0;
    const int jt_lo = lo_j >> 6;
    const int jt_hi = q0 >> 6;

    for (int jt = jt_lo; jt <= jt_hi; jt++) {
        const int j0 = jt << 6;
        __syncthreads();
#pragma unroll
        for (int it = 0; it < 8; it++) {
            int e = tid + 128 * it;
            {
                int row = e >> 4, c = e & 15;
                size_t gb = ((size_t)(j0 + row) * NKV + hk) * HD + c * 8;
                *(uint4*)&Khi[row * RSQ + c * 4] = *(const uint4*)(khi + gb);
                *(uint4*)&Klo[row * RSQ + c * 4] = *(const uint4*)(klo + gb);
            }
            {
                int d = e >> 3, c = e & 7;
                size_t gb = ((size_t)hk * HD + d) * S_LEN + j0 + c * 8;
                *(uint4*)&Vhi[d * RSV + c * 4] = *(const uint4*)(vthi + gb);
                *(uint4*)&Vlo[d * RSV + c * 4] = *(const uint4*)(vtlo + gb);
            }
        }
        __syncthreads();

        float sacc[8][4];
#pragma unroll
        for (int n = 0; n < 8; n++)
#pragma unroll
            for (int c = 0; c < 4; c++) sacc[n][c] = 0.f;

#pragma unroll
        for (int kt = 0; kt < 8; kt++) {
            int ao = (wrow + g) * RSQ + kt * 8 + t4;
            u32 qh0 = Qhi[ao];
            u32 qh1 = Qhi[ao + 8 * RSQ];
            u32 qh2 = Qhi[ao + 4];
            u32 qh3 = Qhi[ao + 8 * RSQ + 4];
            u32 ql0 = Qlo[ao];
            u32 ql1 = Qlo[ao + 8 * RSQ];
            u32 ql2 = Qlo[ao + 4];
            u32 ql3 = Qlo[ao + 8 * RSQ + 4];
#pragma unroll
            for (int nt = 0; nt < 8; nt++) {
                int bo = (nt * 8 + g) * RSQ + kt * 8 + t4;
                u32 bh0 = Khi[bo], bh1 = Khi[bo + 4];
                u32 bl0 = Klo[bo], bl1 = Klo[bo + 4];
                MMA_BF16(sacc[nt], qh0, qh1, qh2, qh3, bh0, bh1);
                MMA_BF16(sacc[nt], qh0, qh1, qh2, qh3, bl0, bl1);
                MMA_BF16(sacc[nt], ql0, ql1, ql2, ql3, bh0, bh1);
            }
        }

        bool full = (j0 + 63 <= q0 + wrow) && (j0 > q0 + wrow + 15 - WINDOW);
        if (full) {
#pragma unroll
            for (int nt = 0; nt < 8; nt++)
#pragma unroll
                for (int c = 0; c < 4; c++) sacc[nt][c] *= SCALE_F;
        } else {
#pragma unroll
            for (int nt = 0; nt < 8; nt++) {
                int jb = j0 + nt * 8 + 2 * t4;
                bool a00 = (jb     <= i0) && (jb     > i0 - WINDOW);
                bool a01 = (jb + 1 <= i0) && (jb + 1 > i0 - WINDOW);
                bool a10 = (jb     <= i1) && (jb     > i1 - WINDOW);
                bool a11 = (jb + 1 <= i1) && (jb + 1 > i1 - WINDOW);
                sacc[nt][0] = a00 ? sacc[nt][0] * SCALE_F : NEGINF;
                sacc[nt][1] = a01 ? sacc[nt][1] * SCALE_F : NEGINF;
                sacc[nt][2] = a10 ? sacc[nt][2] * SCALE_F : NEGINF;
                sacc[nt][3] = a11 ? sacc[nt][3] * SCALE_F : NEGINF;
            }
        }

        float mx0 = -1e30f, mx1 = -1e30f;
#pragma unroll
        for (int nt = 0; nt < 8; nt++) {
            mx0 = fmaxf(mx0, fmaxf(sacc[nt][0], sacc[nt][1]));
            mx1 = fmaxf(mx1, fmaxf(sacc[nt][2], sacc[nt][3]));
        }
        mx0 = fmaxf(mx0, __shfl_xor_sync(0xffffffffu, mx0, 1));
        mx0 = fmaxf(mx0, __shfl_xor_sync(0xffffffffu, mx0, 2));
        mx1 = fmaxf(mx1, __shfl_xor_sync(0xffffffffu, mx1, 1));
        mx1 = fmaxf(mx1, __shfl_xor_sync(0xffffffffu, mx1, 2));
        float mn0 = fmaxf(m0, mx0);
        float mn1 = fmaxf(m1, mx1);
        float f0 = __expf(m0 - mn0);
        float f1 = __expf(m1 - mn1);
        float sum0 = 0.f, sum1 = 0.f;
#pragma unroll
        for (int nt = 0; nt < 8; nt++) {
            sacc[nt][0] = __expf(sacc[nt][0] - mn0); sum0 += sacc[nt][0];
            sacc[nt][1] = __expf(sacc[nt][1] - mn0); sum0 += sacc[nt][1];
            sacc[nt][2] = __expf(sacc[nt][2] - mn1); sum1 += sacc[nt][2];
            sacc[nt][3] = __expf(sacc[nt][3] - mn1); sum1 += sacc[nt][3];
        }
        sum0 += __shfl_xor_sync(0xffffffffu, sum0, 1);
        sum0 += __shfl_xor_sync(0xffffffffu, sum0, 2);
        sum1 += __shfl_xor_sync(0xffffffffu, sum1, 1);
        sum1 += __shfl_xor_sync(0xffffffffu, sum1, 2);
        l0 = l0 * f0 + sum0;  m0 = mn0;
        l1 = l1 * f1 + sum1;  m1 = mn1;

#pragma unroll
        for (int n = 0; n < 16; n++) {
            oacc[n][0] *= f0; oacc[n][1] *= f0;
            oacc[n][2] *= f1; oacc[n][3] *= f1;
        }

#pragma unroll
        for (int kt = 0; kt < 4; kt++) {
            float p00 = sacc[2*kt][0],   p01 = sacc[2*kt][1];
            float p02 = sacc[2*kt][2],   p03 = sacc[2*kt][3];
            float p10 = sacc[2*kt+1][0], p11 = sacc[2*kt+1][1];
            float p12 = sacc[2*kt+1][2], p13 = sacc[2*kt+1][3];
            float h00 = __bfloat162float(__float2bfloat16_rn(p00));
            float h01 = __bfloat162float(__float2bfloat16_rn(p01));
            float h02 = __bfloat162float(__float2bfloat16_rn(p02));
            float h03 = __bfloat162float(__float2bfloat16_rn(p03));
            float h10 = __bfloat162float(__float2bfloat16_rn(p10));
            float h11 = __bfloat162float(__float2bfloat16_rn(p11));
            float h12 = __bfloat162float(__float2bfloat16_rn(p12));
            float h13 = __bfloat162float(__float2bfloat16_rn(p13));
            u32 ah0 = pack_bf16(h00, h01);
            u32 ah1 = pack_bf16(h02, h03);
            u32 ah2 = pack_bf16(h10, h11);
            u32 ah3 = pack_bf16(h12, h13);
            u32 al0 = pack_bf16(p00 - h00, p01 - h01);
            u32 al1 = pack_bf16(p02 - h02, p03 - h03);
            u32 al2 = pack_bf16(p10 - h10, p11 - h11);
            u32 al3 = pack_bf16(p12 - h12, p13 - h13);
#pragma unroll
            for (int nt = 0; nt < 16; nt++) {
                int vo = (nt * 8 + g) * RSV + kt * 8 + t4;
                u32 vh0 = Vhi[vo], vh1 = Vhi[vo + 4];
                u32 vl0 = Vlo[vo], vl1 = Vlo[vo + 4];
                MMA_BF16(oacc[nt], ah0, ah1, ah2, ah3, vh0, vh1);
                MMA_BF16(oacc[nt], ah0, ah1, ah2, ah3, vl0, vl1);
                MMA_BF16(oacc[nt], al0, al1, al2, al3, vh0, vh1);
            }
        }
    }

    // ---- epilogue: write pre-split pair-words for the O-projection ----
    float inv0 = 1.0f / l0;
    float inv1 = 1.0f / l1;
#pragma unroll
    for (int nt = 0; nt < 16; nt++) {
        int col = nt * 8 + 2 * t4;                     // even column in head
        int wcol = (h * HD + col) >> 1;                // pair-word column
        size_t w0 = (size_t)i0 * (HID / 2) + wcol;
        size_t w1 = (size_t)i1 * (HID / 2) + wcol;
        u32 hi0, lo0, hi1, lo1;
        split_pair(oacc[nt][0] * inv0, oacc[nt][1] * inv0, hi0, lo0);
        split_pair(oacc[nt][2] * inv1, oacc[nt][3] * inv1, hi1, lo1);
        athi[w0] = hi0;  atlo[w0] = lo0;
        athi[w1] = hi1;  atlo[w1] = lo1;
    }
}

// ---------------------------------------------------------------------------
// kernel_launch
// ---------------------------------------------------------------------------
extern "C" void kernel_launch(void* const* d_in, const int* in_sizes, int n_in,
                              void* d_out, int out_size)
{
    (void)in_sizes; (void)n_in; (void)out_size;
    const float* hs = (const float*)d_in[0];
    const float* Wq = (const float*)d_in[3];
    const float* Wk = (const float*)d_in[4];
    const float* Wv = (const float*)d_in[5];
    const float* Wo = (const float*)d_in[6];
    float* out = (float*)d_out;

    float *q, *k, *v;
    __nv_bfloat16 *qhi, *qlo, *khi, *klo, *vthi, *vtlo;
    u32 *hshi, *hslo, *wqhi, *wqlo, *wkhi, *wklo, *wvhi, *wvlo, *wohi, *wolo;
    u32 *athi, *atlo;
    cudaGetSymbolAddress((void**)&q,    g_q);
    cudaGetSymbolAddress((void**)&k,    g_k);
    cudaGetSymbolAddress((void**)&v,    g_v);
    cudaGetSymbolAddress((void**)&qhi,  g_qhi);
    cudaGetSymbolAddress((void**)&qlo,  g_qlo);
    cudaGetSymbolAddress((void**)&khi,  g_khi);
    cudaGetSymbolAddress((void**)&klo,  g_klo);
    cudaGetSymbolAddress((void**)&vthi, g_vthi);
    cudaGetSymbolAddress((void**)&vtlo, g_vtlo);
    cudaGetSymbolAddress((void**)&hshi, g_hshi);
    cudaGetSymbolAddress((void**)&hslo, g_hslo);
    cudaGetSymbolAddress((void**)&wqhi, g_wqhi);
    cudaGetSymbolAddress((void**)&wqlo, g_wqlo);
    cudaGetSymbolAddress((void**)&wkhi, g_wkhi);
    cudaGetSymbolAddress((void**)&wklo, g_wklo);
    cudaGetSymbolAddress((void**)&wvhi, g_wvhi);
    cudaGetSymbolAddress((void**)&wvlo, g_wvlo);
    cudaGetSymbolAddress((void**)&wohi, g_wohi);
    cudaGetSymbolAddress((void**)&wolo, g_wolo);
    cudaGetSymbolAddress((void**)&athi, g_athi);
    cudaGetSymbolAddress((void**)&atlo, g_atlo);

    cudaFuncSetAttribute(gemm_pre,
                         cudaFuncAttributeMaxDynamicSharedMemorySize, GEMM_SMEM_BYTES);
    const int att_smem = ATT_SMEM_WORDS * (int)sizeof(u32);
    cudaFuncSetAttribute(attn_mma_kernel,
                         cudaFuncAttributeMaxDynamicSharedMemorySize, att_smem);

    // ---- operand pre-split ----
    {
        int wA = S_LEN * HID / 2;
        split_A_kernel<<<(wA + 255) / 256, 256>>>(hs, hshi, hslo, wA);
        int wQ = (HID / 2) * (NH * HD);
        split_B_kernel<<<(wQ + 255) / 256, 256>>>(Wq, wqhi, wqlo, HID / 2, NH * HD);
        int wK = (HID / 2) * (NKV * HD);
        split_B_kernel<<<(wK + 255) / 256, 256>>>(Wk, wkhi, wklo, HID / 2, NKV * HD);
        split_B_kernel<<<(wK + 255) / 256, 256>>>(Wv, wvhi, wvlo, HID / 2, NKV * HD);
        int wO = (NH * HD / 2) * HID;
        split_B_kernel<<<(wO + 255) / 256, 256>>>(Wo, wohi, wolo, NH * HD / 2, HID);
    }

    // ---- projections ----
    gemm_pre<<<dim3((NH*HD) / 128, S_LEN / 128), 256, GEMM_SMEM_BYTES>>>(
        hshi, hslo, wqhi, wqlo, q, S_LEN, NH * HD, HID / 2);
    gemm_pre<<<dim3((NKV*HD) / 128, S_LEN / 128), 256, GEMM_SMEM_BYTES>>>(
        hshi, hslo, wkhi, wklo, k, S_LEN, NKV * HD, HID / 2);
    gemm_pre<<<dim3((NKV*HD) / 128, S_LEN / 128), 256, GEMM_SMEM_BYTES>>>(
        hshi, hslo, wvhi, wvlo, v, S_LEN, NKV * HD, HID / 2);

    // ---- RoPE + splits ----
    rope_tables_kernel<<<S_LEN, 64>>>();
    rope_split_kernel<<<(S_LEN * NH  * 64 + 255) / 256, 256>>>(q, qhi, qlo, NH);
    rope_split_kernel<<<(S_LEN * NKV * 64 + 255) / 256, 256>>>(k, khi, klo, NKV);
    v_split_transpose_kernel<<<dim3(S_LEN / 32, HD / 32, NKV), dim3(32, 8)>>>();

    // ---- attention ----
    attn_mma_kernel<<<dim3(S_LEN / 64, NH), 128, att_smem>>>(
        qhi, qlo, khi, klo, vthi, vtlo, athi, atlo);

    // ---- output projection ----
    gemm_pre<<<dim3(HID / 128, S_LEN / 128), 256, GEMM_SMEM_BYTES>>>(
        athi, atlo, wohi, wolo, out, S_LEN, HID, NH * HD / 2);
}